// round 5
// baseline (speedup 1.0000x reference)
#include <cuda_runtime.h>
#include <cuda_bf16.h>

// Welford running mean/variance over batch dim of x: (B, C, H, W), B=256, CHW=262144.
// One scalar thread per spatial position (262,144 threads), exact sequential Welford.
// KEY CHANGE vs R1: per outer step, load K=8 batch samples into DISTINCT registers
// (8 independent LDGs in flight) BEFORE storing/consuming them — breaks the
// LDG->STG->LDG register-reuse WAR chain that serialized every prior round at MLP=1.
//
// Output layout (float32, concatenated):
//   [0, B*CHW)     : x passthrough
//   [+0, +CHW)     : m
//   [+CHW, +2CHW)  : s
//   [+2CHW, +3CHW) : neuron_nonzero (int -> float)
//   [last]         : n_samples + B

#define KBATCH 8

__global__ void __launch_bounds__(256) welford_kernel_mlp(
    const float* __restrict__ x,
    const float* __restrict__ m_in,
    const float* __restrict__ s_in,
    const int*   __restrict__ nn_in,
    const int*   __restrict__ n_in,
    float*       __restrict__ out,
    int B, int CHW)
{
    int p = blockIdx.x * blockDim.x + threadIdx.x;
    if (p >= CHW) return;

    float m  = m_in[p];
    float s  = s_in[p];
    int   nn = nn_in[p];
    const int n0 = n_in[0];

    const float* xp = x + p;
    float*       op = out + p;

    for (int b = 0; b < B; b += KBATCH) {
        // Phase 1: issue KBATCH independent loads into distinct registers.
        float xs[KBATCH];
        #pragma unroll
        for (int j = 0; j < KBATCH; ++j) {
            xs[j] = xp[(size_t)(b + j) * CHW];
        }

        // Phase 2: passthrough stores + exact sequential Welford update.
        #pragma unroll
        for (int j = 0; j < KBATCH; ++j) {
            float xv = xs[j];
            op[(size_t)(b + j) * CHW] = xv;

            nn += (xv != 0.0f);
            float old_m = m;
            float inv = __fdividef(1.0f, (float)(n0 + b + j + 1));
            m = m + (xv - m) * inv;
            s = s + (xv - m) * (xv - old_m);
        }
    }

    size_t base = (size_t)B * (size_t)CHW;
    out[base + p]                   = m;
    out[base + (size_t)CHW + p]     = s;
    out[base + 2 * (size_t)CHW + p] = (float)nn;
    if (p == 0) {
        out[base + 3 * (size_t)CHW] = (float)(n0 + B);
    }
}

extern "C" void kernel_launch(void* const* d_in, const int* in_sizes, int n_in,
                              void* d_out, int out_size)
{
    const float* x  = (const float*)d_in[0];
    const float* m  = (const float*)d_in[1];
    const float* s  = (const float*)d_in[2];
    const int*   nn = (const int*)d_in[3];
    const int*   n  = (const int*)d_in[4];
    float* out = (float*)d_out;

    const int CHW = in_sizes[1];          // 262144
    const int B   = in_sizes[0] / CHW;    // 256

    const int threads = 256;
    const int blocks = (CHW + threads - 1) / threads;  // 1024
    welford_kernel_mlp<<<blocks, threads>>>(x, m, s, nn, n, out, B, CHW);
}

// round 6
// speedup vs baseline: 1.0007x; 1.0007x over previous
#include <cuda_runtime.h>
#include <cuda_bf16.h>

// Welford running mean/variance over batch dim of x: (B, C, H, W), B=256, CHW=262144.
// One scalar thread per spatial position (262,144 threads), exact sequential Welford.
//
// R6 change: __launch_bounds__(256, 4) raises the per-thread register ceiling to 64,
// so the KBATCH=8 front-batched loads live in 8 DISTINCT registers (true MLP~8).
// In R1-R5 ptxas capped regs at 32 (occupancy default) and re-serialized the loads
// back to a rolling register (MLP~1), which is why DRAM%% never moved.
//
// Output layout (float32, concatenated):
//   [0, B*CHW)     : x passthrough
//   [+0, +CHW)     : m
//   [+CHW, +2CHW)  : s
//   [+2CHW, +3CHW) : neuron_nonzero (int -> float)
//   [last]         : n_samples + B

#define KBATCH 8

__global__ void __launch_bounds__(256, 4) welford_kernel_mlp64(
    const float* __restrict__ x,
    const float* __restrict__ m_in,
    const float* __restrict__ s_in,
    const int*   __restrict__ nn_in,
    const int*   __restrict__ n_in,
    float*       __restrict__ out,
    int B, int CHW)
{
    int p = blockIdx.x * blockDim.x + threadIdx.x;
    if (p >= CHW) return;

    float m  = m_in[p];
    float s  = s_in[p];
    int   nn = nn_in[p];
    const int n0 = n_in[0];

    const float* xp = x + p;
    float*       op = out + p;

    for (int b = 0; b < B; b += KBATCH) {
        // Phase 1: KBATCH independent loads into distinct registers (front-batched).
        float xs[KBATCH];
        #pragma unroll
        for (int j = 0; j < KBATCH; ++j) {
            xs[j] = xp[(size_t)(b + j) * CHW];
        }

        // Phase 2: passthrough stores + exact sequential Welford update.
        #pragma unroll
        for (int j = 0; j < KBATCH; ++j) {
            float xv = xs[j];
            op[(size_t)(b + j) * CHW] = xv;

            nn += (xv != 0.0f);
            float old_m = m;
            float inv = __fdividef(1.0f, (float)(n0 + b + j + 1));
            m = m + (xv - m) * inv;
            s = s + (xv - m) * (xv - old_m);
        }
    }

    size_t base = (size_t)B * (size_t)CHW;
    out[base + p]                   = m;
    out[base + (size_t)CHW + p]     = s;
    out[base + 2 * (size_t)CHW + p] = (float)nn;
    if (p == 0) {
        out[base + 3 * (size_t)CHW] = (float)(n0 + B);
    }
}

extern "C" void kernel_launch(void* const* d_in, const int* in_sizes, int n_in,
                              void* d_out, int out_size)
{
    const float* x  = (const float*)d_in[0];
    const float* m  = (const float*)d_in[1];
    const float* s  = (const float*)d_in[2];
    const int*   nn = (const int*)d_in[3];
    const int*   n  = (const int*)d_in[4];
    float* out = (float*)d_out;

    const int CHW = in_sizes[1];          // 262144
    const int B   = in_sizes[0] / CHW;    // 256

    const int threads = 256;
    const int blocks = (CHW + threads - 1) / threads;  // 1024
    welford_kernel_mlp64<<<blocks, threads>>>(x, m, s, nn, n, out, B, CHW);
}